// round 14
// baseline (speedup 1.0000x reference)
#include <cuda_runtime.h>
#include <cuda_fp16.h>
#include <math.h>

#define NN 20000
#define NE 640000
#define NB 4
#define NS 12
#define HD 64
#define DEG_CAP 96
#define FULL 0xffffffffu

// ---------------- scratch ----------------
__device__ float    g_h [NB * NN * HD];
__device__ __half2  g_xeh[NB * NN * 32];
__device__ float    g_es[NB * NN * 8];
__device__ float    g_ed[NB * NN * 8];
__device__ unsigned g_mx[3][32];
__device__ float    g_fold[16 * 64];
__device__ float    g_cfold[64];
__device__ unsigned g_cwt[192 * 65];
__device__ int      g_cnt[NN];            // zero-init at load; scan re-zeroes each run
__device__ int      g_rank[NE];
__device__ int      g_rowptr[NN + 1];
__device__ int      g_csr[NE];

__device__ __forceinline__ float lrelu(float v) { return v > 0.f ? v : 0.2f * v; }

__device__ __forceinline__ unsigned encf(float f) {
    unsigned u = __float_as_uint(f);
    return (u & 0x80000000u) ? ~u : (u | 0x80000000u);
}
__device__ __forceinline__ float decf(unsigned u) {
    return (u & 0x80000000u) ? __uint_as_float(u ^ 0x80000000u) : __uint_as_float(~u);
}

__device__ __forceinline__ unsigned f2tf32(float v) {
    unsigned u;
    asm("cvt.rna.tf32.f32 %0, %1;" : "=r"(u) : "f"(v));
    return u;
}

__device__ __forceinline__ void mma_tf32(float c[4], unsigned a0, unsigned a1,
                                         unsigned a2, unsigned a3,
                                         unsigned b0, unsigned b1) {
    asm("mma.sync.aligned.m16n8k8.row.col.f32.tf32.tf32.f32 "
        "{%0,%1,%2,%3},{%4,%5,%6,%7},{%8,%9},{%0,%1,%2,%3};"
        : "+f"(c[0]), "+f"(c[1]), "+f"(c[2]), "+f"(c[3])
        : "r"(a0), "r"(a1), "r"(a2), "r"(a3), "r"(b0), "r"(b1));
}

// PDL controls (no-ops when launched without programmatic serialization)
__device__ __forceinline__ void gdep_wait()   { asm volatile("griddepcontrol.wait;" ::: "memory"); }
__device__ __forceinline__ void gdep_launch() { asm volatile("griddepcontrol.launch_dependents;" ::: "memory"); }

// ---------------- CSR build (side-stream branch) ----------------
__global__ __launch_bounds__(256) void k_hist(const int* __restrict__ ei,
                                              const float* __restrict__ cw) {
    if (blockIdx.x < 2500) {
        int e = blockIdx.x * 256 + threadIdx.x;
        if (e < NE) g_rank[e] = atomicAdd(&g_cnt[ei[NE + e]], 1);
    } else {
        for (int t = threadIdx.x; t < 64 * 192; t += 256) {
            int o = t / 192, ka = t % 192;
            g_cwt[ka * 65 + o] = f2tf32(cw[t]);
        }
    }
}

__global__ __launch_bounds__(1024) void k_scan() {
    __shared__ int sh[1024];
    int t = threadIdx.x;
    const int CH = (NN + 1023) / 1024;
    int base = t * CH;
    int s = 0;
    for (int j = 0; j < CH; j++) {
        int idx = base + j;
        if (idx < NN) s += g_cnt[idx];
    }
    sh[t] = s;
    __syncthreads();
    for (int d = 1; d < 1024; d <<= 1) {
        int v = (t >= d) ? sh[t - d] : 0;
        __syncthreads();
        sh[t] += v;
        __syncthreads();
    }
    int run = sh[t] - s;
    for (int j = 0; j < CH; j++) {
        int idx = base + j;
        if (idx < NN) {
            int c = g_cnt[idx];
            g_rowptr[idx] = run;
            run += c;
            g_cnt[idx] = 0;
        }
    }
    if (t == 1023) g_rowptr[NN] = sh[1023];
}

__global__ __launch_bounds__(256) void k_scatter(const int* __restrict__ ei) {
    int e = blockIdx.x * 256 + threadIdx.x;
    if (e < NE) {
        int d = ei[NE + e];
        g_csr[g_rowptr[d] + g_rank[e]] = ei[e];
    }
}

__global__ __launch_bounds__(256) void k_sort() {
    __shared__ int s_v[8][DEG_CAP];
    int w = threadIdx.x >> 5, lane = threadIdx.x & 31;
    int node = blockIdx.x * 8 + w;
    if (node >= NN) return;
    int start = g_rowptr[node];
    int deg = g_rowptr[node + 1] - start;
    if (deg <= 1) return;
    if (deg <= DEG_CAP) {
        for (int j = lane; j < deg; j += 32) s_v[w][j] = g_csr[start + j];
        __syncwarp();
        for (int j = lane; j < deg; j += 32) {
            int v = s_v[w][j];
            int pos = 0;
            for (int k = 0; k < deg; k++) {
                int u = s_v[w][k];
                pos += (u < v) || (u == v && k < j);
            }
            g_csr[start + pos] = v;
        }
    } else if (lane == 0) {   // statistically impossible fallback
        for (int a = start + 1; a < start + deg; a++) {
            int v = g_csr[a];
            int b = a - 1;
            while (b >= start && g_csr[b] > v) { g_csr[b + 1] = g_csr[b]; b--; }
            g_csr[b + 1] = v;
        }
    }
}

// ---------------- fold (main branch): pw@W0, pb@W0; zeroes g_mx ----------------
__global__ __launch_bounds__(256) void k_fold(const float* __restrict__ pw,
                                              const float* __restrict__ pb,
                                              const float* __restrict__ W) {
    int tid = threadIdx.x;
    if (tid < 96) ((unsigned*)g_mx)[tid] = 0;
    for (int i = tid; i < 1024; i += 256) {
        int s = i >> 6, o = i & 63;
        float acc = 0.f;
        if (s < NS)
            for (int k = 0; k < 64; k++) acc += pw[s * 64 + k] * W[k * 64 + o];
        g_fold[i] = acc;
    }
    if (tid < 64) {
        float a = 0.f;
        for (int k = 0; k < 64; k++) a += pb[k] * W[k * 64 + tid];
        g_cfold[tid] = a;
    }
}

// ---------------- mma gemm epilogue ----------------
template <int H>
__device__ __forceinline__ void mma_epilogue(float c[8][4], int n0, int b, int lane,
                                             const float2* as_sh, const float2* ad_sh,
                                             unsigned* smax_sh, int which) {
    int g = lane >> 2, tq = lane & 3;
    int nA = n0 + g, nB = n0 + g + 8;
    #pragma unroll
    for (int nt = 0; nt < 8; nt++) {
        g_xeh[((size_t)nA * NB + b) * 32 + nt * 4 + tq] = __floats2half2_rn(c[nt][0], c[nt][1]);
        g_xeh[((size_t)nB * NB + b) * 32 + nt * 4 + tq] = __floats2half2_rn(c[nt][2], c[nt][3]);
    }
    if (H == 8) {
        float keep[8];
        #pragma unroll
        for (int nt = 0; nt < 8; nt++) {
            float2 av = as_sh[nt * 4 + tq];
            float2 dv = ad_sh[nt * 4 + tq];
            float eA = c[nt][0] * av.x + c[nt][1] * av.y;
            float eB = c[nt][2] * av.x + c[nt][3] * av.y;
            float dA = c[nt][0] * dv.x + c[nt][1] * dv.y;
            float dB = c[nt][2] * dv.x + c[nt][3] * dv.y;
            eA += __shfl_xor_sync(FULL, eA, 1); eA += __shfl_xor_sync(FULL, eA, 2);
            eB += __shfl_xor_sync(FULL, eB, 1); eB += __shfl_xor_sync(FULL, eB, 2);
            dA += __shfl_xor_sync(FULL, dA, 1); dA += __shfl_xor_sync(FULL, dA, 2);
            dB += __shfl_xor_sync(FULL, dB, 1); dB += __shfl_xor_sync(FULL, dB, 2);
            if ((nt & 3) == tq) {
                int hi = nt >> 2;
                keep[hi * 4 + 0] = eA; keep[hi * 4 + 1] = eB;
                keep[hi * 4 + 2] = dA; keep[hi * 4 + 3] = dB;
            }
        }
        g_es[(size_t)nA * 32 + b * 8 + tq]     = keep[0];
        g_es[(size_t)nB * 32 + b * 8 + tq]     = keep[1];
        g_ed[(size_t)nA * 32 + b * 8 + tq]     = keep[2];
        g_ed[(size_t)nB * 32 + b * 8 + tq]     = keep[3];
        g_es[(size_t)nA * 32 + b * 8 + tq + 4] = keep[4];
        g_es[(size_t)nB * 32 + b * 8 + tq + 4] = keep[5];
        g_ed[(size_t)nA * 32 + b * 8 + tq + 4] = keep[6];
        g_ed[(size_t)nB * 32 + b * 8 + tq + 4] = keep[7];
        float mA = fmaxf(keep[0], keep[1]);
        float mB = fmaxf(keep[4], keep[5]);
        #pragma unroll
        for (int d = 4; d < 32; d <<= 1) {
            mA = fmaxf(mA, __shfl_xor_sync(FULL, mA, d));
            mB = fmaxf(mB, __shfl_xor_sync(FULL, mB, d));
        }
        if (g == 0) {
            atomicMax(&smax_sh[which * 8 + tq], encf(mA));
            atomicMax(&smax_sh[which * 8 + tq + 4], encf(mB));
        }
    } else {
        float eA = 0.f, eB = 0.f, dA = 0.f, dB = 0.f;
        #pragma unroll
        for (int nt = 0; nt < 8; nt++) {
            float2 av = as_sh[nt * 4 + tq];
            float2 dv = ad_sh[nt * 4 + tq];
            eA += c[nt][0] * av.x + c[nt][1] * av.y;
            eB += c[nt][2] * av.x + c[nt][3] * av.y;
            dA += c[nt][0] * dv.x + c[nt][1] * dv.y;
            dB += c[nt][2] * dv.x + c[nt][3] * dv.y;
        }
        eA += __shfl_xor_sync(FULL, eA, 1); eA += __shfl_xor_sync(FULL, eA, 2);
        eB += __shfl_xor_sync(FULL, eB, 1); eB += __shfl_xor_sync(FULL, eB, 2);
        dA += __shfl_xor_sync(FULL, dA, 1); dA += __shfl_xor_sync(FULL, dA, 2);
        dB += __shfl_xor_sync(FULL, dB, 1); dB += __shfl_xor_sync(FULL, dB, 2);
        if (tq == 0) {
            g_es[(size_t)nA * 4 + b] = eA;
            g_es[(size_t)nB * 4 + b] = eB;
            g_ed[(size_t)nA * 4 + b] = dA;
            g_ed[(size_t)nB * 4 + b] = dB;
        }
        float m = fmaxf(eA, eB);
        #pragma unroll
        for (int d = 4; d < 32; d <<= 1) m = fmaxf(m, __shfl_xor_sync(FULL, m, d));
        if (lane == 0) atomicMax(&smax_sh[which * 8], encf(m));
    }
}

// ---------------- gemm layers 1,2 (PDL: W prologue pre-wait, g_h post-wait) ----------------
#define GEMM_DYN ((4096 + 8 * 1088) * 4)

template <int H>
__global__ __launch_bounds__(256) void k_gemm_mma(const float* __restrict__ W,
                                                  const float* __restrict__ asrc,
                                                  const float* __restrict__ adst,
                                                  int layer) {
    extern __shared__ unsigned dynsh[];
    uint2* wfrag = (uint2*)dynsh;
    unsigned* hst = dynsh + 4096;
    __shared__ float2 as_sh[32], ad_sh[32];
    __shared__ unsigned smax_sh[16];
    int tid = threadIdx.x, w = tid >> 5, lane = tid & 31, g = lane >> 2, tq = lane & 3;
    gdep_launch();                              // let successor board early
    for (int i = tid; i < 4096; i += 256) {     // input-only prologue
        int k = i >> 6, o = i & 63;
        unsigned val = f2tf32(__ldg(&W[i]));
        int slot = ((k >> 3) * 8 + (o >> 3)) * 32 + (o & 7) * 4 + (k & 3);
        ((unsigned*)wfrag)[slot * 2 + ((k >> 2) & 1)] = val;
    }
    if (tid < 32) { as_sh[tid] = ((const float2*)asrc)[tid]; ad_sh[tid] = ((const float2*)adst)[tid]; }
    if (tid < 16) smax_sh[tid] = 0;
    gdep_wait();                                // predecessor's g_h now final
    int idxw = blockIdx.x * 128 + w * 16;
    int b = idxw / NN, n0 = idxw - b * NN;
    {
        const float4* gh4 = (const float4*)g_h;
        uint4* hs4 = (uint4*)(hst + w * 1088);
        #pragma unroll
        for (int j = 0; j < 8; j++) {
            int i4 = lane + 32 * j;
            int node = i4 >> 4, c4 = i4 & 15;
            float4 v = gh4[((size_t)idxw + node) * 16 + c4];
            uint4 u;
            u.x = f2tf32(v.x); u.y = f2tf32(v.y); u.z = f2tf32(v.z); u.w = f2tf32(v.w);
            hs4[node * 17 + c4] = u;
        }
    }
    __syncthreads();
    float c[8][4];
    #pragma unroll
    for (int nt = 0; nt < 8; nt++)
        c[nt][0] = c[nt][1] = c[nt][2] = c[nt][3] = 0.f;
    unsigned* hs = hst + w * 1088;
    #pragma unroll
    for (int kc = 0; kc < 8; kc++) {
        unsigned a0 = hs[g * 68 + kc * 8 + tq];
        unsigned a1 = hs[(g + 8) * 68 + kc * 8 + tq];
        unsigned a2 = hs[g * 68 + kc * 8 + tq + 4];
        unsigned a3 = hs[(g + 8) * 68 + kc * 8 + tq + 4];
        #pragma unroll
        for (int nt = 0; nt < 8; nt++) {
            uint2 bb = wfrag[(kc * 8 + nt) * 32 + lane];
            mma_tf32(c[nt], a0, a1, a2, a3, bb.x, bb.y);
        }
    }
    int bfirst = (blockIdx.x * 128) / NN;
    mma_epilogue<H>(c, n0, b, lane, as_sh, ad_sh, smax_sh, b - bfirst);
    __syncthreads();
    if (tid < 16) {
        int which = tid >> 3, h = tid & 7;
        int bt = bfirst + which;
        unsigned v = smax_sh[tid];
        if (bt < NB && v != 0 && (H == 8 || h == 0))
            atomicMax(&g_mx[layer][(H == 8) ? bt * 8 + h : bt], v);
    }
}

// ---------------- layer 0 gemm (plain; predecessor k_fold is tiny) ----------------
__global__ __launch_bounds__(256) void k_gemm0_mma(const float* __restrict__ x,
                                                   const float* __restrict__ asrc,
                                                   const float* __restrict__ adst) {
    __shared__ uint2 wfrag[512];
    __shared__ unsigned xst[8][320];
    __shared__ float2 as_sh[32], ad_sh[32];
    __shared__ float cf_sh[64];
    __shared__ unsigned smax_sh[16];
    int tid = threadIdx.x, w = tid >> 5, lane = tid & 31, g = lane >> 2, tq = lane & 3;
    gdep_launch();
    for (int i = tid; i < 1024; i += 256) {
        int k = i >> 6, o = i & 63;
        unsigned val = f2tf32(g_fold[i]);
        int slot = ((k >> 3) * 8 + (o >> 3)) * 32 + (o & 7) * 4 + (k & 3);
        ((unsigned*)wfrag)[slot * 2 + ((k >> 2) & 1)] = val;
    }
    if (tid < 32) { as_sh[tid] = ((const float2*)asrc)[tid]; ad_sh[tid] = ((const float2*)adst)[tid]; }
    if (tid < 64) cf_sh[tid] = g_cfold[tid];
    if (tid < 16) smax_sh[tid] = 0;
    int idxw = blockIdx.x * 128 + w * 16;
    int b = idxw / NN, n0 = idxw - b * NN;
    #pragma unroll
    for (int j = 0; j < 8; j++) {
        int i2 = lane + 32 * j;
        int s = i2 >> 4, node = i2 & 15;
        unsigned val = 0;
        if (s < NS) val = f2tf32(__ldg(&x[(size_t)(b * NS + s) * NN + n0 + node]));
        xst[w][node * 20 + s] = val;
    }
    __syncthreads();
    float c[8][4];
    #pragma unroll
    for (int nt = 0; nt < 8; nt++)
        c[nt][0] = c[nt][1] = c[nt][2] = c[nt][3] = 0.f;
    #pragma unroll
    for (int kc = 0; kc < 2; kc++) {
        unsigned a0 = xst[w][g * 20 + kc * 8 + tq];
        unsigned a1 = xst[w][(g + 8) * 20 + kc * 8 + tq];
        unsigned a2 = xst[w][g * 20 + kc * 8 + tq + 4];
        unsigned a3 = xst[w][(g + 8) * 20 + kc * 8 + tq + 4];
        #pragma unroll
        for (int nt = 0; nt < 8; nt++) {
            uint2 bb = wfrag[(kc * 8 + nt) * 32 + lane];
            mma_tf32(c[nt], a0, a1, a2, a3, bb.x, bb.y);
        }
    }
    #pragma unroll
    for (int nt = 0; nt < 8; nt++) {
        float c0 = cf_sh[nt * 8 + 2 * tq], c1 = cf_sh[nt * 8 + 2 * tq + 1];
        c[nt][0] += c0; c[nt][1] += c1;
        c[nt][2] += c0; c[nt][3] += c1;
    }
    int bfirst = (blockIdx.x * 128) / NN;
    mma_epilogue<8>(c, n0, b, lane, as_sh, ad_sh, smax_sh, b - bfirst);
    __syncthreads();
    if (tid < 16) {
        int which = tid >> 3, h = tid & 7;
        int bt = bfirst + which;
        unsigned v = smax_sh[tid];
        if (bt < NB && v != 0)
            atomicMax(&g_mx[0][bt * 8 + h], v);
    }
}

// ---------------- aggregation (PDL: rowptr pre-wait, ed/mx/loop post-wait) ----------------
template <int H, bool DO_ELU>
__global__ __launch_bounds__(256) void k_agg1p(const float* __restrict__ bias, int layer) {
    int w = threadIdx.x >> 5, lane = threadIdx.x & 31;
    int i = blockIdx.x * 8 + w;
    gdep_launch();
    int start = g_rowptr[i];                 // CSR branch: guarded by full event edge
    int deg = g_rowptr[i + 1] - start;
    int tot = deg + 1;
    int b3 = lane >> 3, ch = lane & 7;
    gdep_wait();                             // gemm's es/ed/xeh/mx now final
    float edv, m;
    if (H == 8) {
        edv = __ldg(&g_ed[(size_t)i * 32 + lane]);
        m = lrelu(decf(g_mx[layer][lane]) + edv);
    } else {
        edv = __ldg(&g_ed[(size_t)i * 4 + b3]);
        m = lrelu(decf(g_mx[2][b3]) + edv);
    }
    float sum = 0.f;
    float a[8];
    #pragma unroll
    for (int k = 0; k < 8; k++) a[k] = 0.f;
    const uint4* __restrict__ xe4 = (const uint4*)g_xeh;
    const int* __restrict__ csr = g_csr + start;

    #pragma unroll 4
    for (int j = 0; j < tot; j++) {
        int s = (j < deg) ? __ldg(&csr[j]) : i;
        float e = (H == 8) ? __ldg(&g_es[(size_t)s * 32 + lane])
                           : __ldg(&g_es[(size_t)s * 4 + b3]);
        float p = __expf(lrelu(e + edv) - m);
        sum += p;
        uint4 v = __ldg(&xe4[(size_t)s * 32 + lane]);
        float2 f0 = __half22float2(*(const __half2*)&v.x);
        float2 f1 = __half22float2(*(const __half2*)&v.y);
        float2 f2 = __half22float2(*(const __half2*)&v.z);
        float2 f3 = __half22float2(*(const __half2*)&v.w);
        a[0] += p * f0.x; a[1] += p * f0.y;
        a[2] += p * f1.x; a[3] += p * f1.y;
        a[4] += p * f2.x; a[5] += p * f2.y;
        a[6] += p * f3.x; a[7] += p * f3.y;
    }

    float inv = 1.f / sum;
    float4 bb0 = ((const float4*)bias)[ch * 2];
    float4 bb1 = ((const float4*)bias)[ch * 2 + 1];
    float o[8];
    o[0] = a[0] * inv + bb0.x; o[1] = a[1] * inv + bb0.y;
    o[2] = a[2] * inv + bb0.z; o[3] = a[3] * inv + bb0.w;
    o[4] = a[4] * inv + bb1.x; o[5] = a[5] * inv + bb1.y;
    o[6] = a[6] * inv + bb1.z; o[7] = a[7] * inv + bb1.w;
    if (DO_ELU) {
        #pragma unroll
        for (int k = 0; k < 8; k++) o[k] = o[k] > 0.f ? o[k] : expm1f(o[k]);
    }
    float4* gh4 = (float4*)g_h;
    size_t obase = ((size_t)(b3 * NN + i)) * 16 + ch * 2;
    gh4[obase]     = make_float4(o[0], o[1], o[2], o[3]);
    gh4[obase + 1] = make_float4(o[4], o[5], o[6], o[7]);
}

// ---------------- conv (PDL: weight copy pre-wait, g_h staging post-wait) ----------------
#define CM 128
#define W_ELE (192 * 65)
#define H_ELE (130 * 65)
#define CONV_SMEM ((W_ELE + H_ELE + 192 + 64) * 4)

__global__ __launch_bounds__(256) void k_conv(const float* __restrict__ cb,
                                              const float* __restrict__ ow,
                                              const float* __restrict__ ob,
                                              float* __restrict__ out) {
    extern __shared__ unsigned cms[];
    unsigned* w_sh = cms;
    unsigned* h_sh = w_sh + W_ELE;
    float* ow_sh = (float*)(h_sh + H_ELE);
    float* cb_sh = ow_sh + 192;
    int tid = threadIdx.x;
    int b = blockIdx.y;
    int n0 = blockIdx.x * CM;

    {
        const uint4* src = (const uint4*)g_cwt;   // old full dep (CSR-branch)
        uint4* dst = (uint4*)w_sh;
        for (int t = tid; t < W_ELE / 4; t += 256) dst[t] = src[t];
    }
    if (tid < 192) ow_sh[tid] = ow[tid];
    if (tid < 64) cb_sh[tid] = cb[tid];
    gdep_wait();                                  // agg2's g_h now final
    for (int t = tid; t < 130 * 64; t += 256) {
        int row = t / 64, c = t % 64;
        int n = n0 - 1 + row;
        float v = (n >= 0 && n < NN) ? g_h[((size_t)(b * NN + n)) * 64 + c] : 0.f;
        h_sh[row * 65 + c] = f2tf32(v);
    }
    __syncthreads();

    int wz = tid >> 5, lane = tid & 31;
    int m0 = wz * 16;
    int g = lane >> 2, tq = lane & 3;
    float c[8][4];
    #pragma unroll
    for (int t = 0; t < 8; t++)
        #pragma unroll
        for (int r = 0; r < 4; r++) c[t][r] = 0.f;

    #pragma unroll 4
    for (int kc = 0; kc < 24; kc++) {
        int ka = kc * 8 + tq;
        int ia = ka / 3, sa = ka % 3;
        int kb = ka + 4;
        int ib = kb / 3, sb = kb % 3;
        unsigned a0 = h_sh[(m0 + g + sa) * 65 + ia];
        unsigned a1 = h_sh[(m0 + g + 8 + sa) * 65 + ia];
        unsigned a2 = h_sh[(m0 + g + sb) * 65 + ib];
        unsigned a3 = h_sh[(m0 + g + 8 + sb) * 65 + ib];
        #pragma unroll
        for (int t = 0; t < 8; t++) {
            unsigned b0 = w_sh[(kc * 8 + tq) * 65 + 8 * t + g];
            unsigned b1 = w_sh[(kc * 8 + tq + 4) * 65 + 8 * t + g];
            mma_tf32(c[t], a0, a1, a2, a3, b0, b1);
        }
    }
    __syncthreads();

    float* v_sh = (float*)h_sh;
    #pragma unroll
    for (int t = 0; t < 8; t++) {
        int n_ = 8 * t + 2 * tq;
        v_sh[(m0 + g) * 65 + n_]     = fmaxf(c[t][0] + cb_sh[n_], 0.f);
        v_sh[(m0 + g) * 65 + n_ + 1] = fmaxf(c[t][1] + cb_sh[n_ + 1], 0.f);
        v_sh[(m0 + g + 8) * 65 + n_]     = fmaxf(c[t][2] + cb_sh[n_], 0.f);
        v_sh[(m0 + g + 8) * 65 + n_ + 1] = fmaxf(c[t][3] + cb_sh[n_ + 1], 0.f);
    }
    __syncthreads();

    float ob0 = ob[0], ob1 = ob[1], ob2 = ob[2];
    for (int task = tid; task < CM * 3; task += 256) {
        int mloc = task / 3, p = task % 3;
        int n = n0 + mloc;
        if (n < NN) {
            float acc = (p == 0) ? ob0 : (p == 1 ? ob1 : ob2);
            #pragma unroll 16
            for (int o = 0; o < 64; o++)
                acc += v_sh[mloc * 65 + o] * ow_sh[o * 3 + p];
            out[((size_t)(b * 3 + p)) * NN + n] = acc;
        }
    }
}

// ---------------- driver ----------------
template <typename F, typename... Args>
static inline void launch_pdl(F f, dim3 grid, dim3 block, size_t smem, Args... args) {
    cudaLaunchConfig_t cfg = {};
    cfg.gridDim = grid;
    cfg.blockDim = block;
    cfg.dynamicSmemBytes = smem;
    cfg.stream = 0;
    cudaLaunchAttribute at[1];
    at[0].id = cudaLaunchAttributeProgrammaticStreamSerialization;
    at[0].val.programmaticStreamSerializationAllowed = 1;
    cfg.attrs = at;
    cfg.numAttrs = 1;
    if (cudaLaunchKernelEx(&cfg, f, args...) != cudaSuccess) {
        cfg.numAttrs = 0;                    // fallback: plain serialized launch
        cudaLaunchKernelEx(&cfg, f, args...);
    }
}

extern "C" void kernel_launch(void* const* d_in, const int* in_sizes, int n_in,
                              void* d_out, int out_size) {
    const float* x    = (const float*)d_in[0];
    const int*   ei   = (const int*)d_in[1];
    const float* pw   = (const float*)d_in[2];
    const float* pb   = (const float*)d_in[3];
    const float* g0w  = (const float*)d_in[4];
    const float* g0as = (const float*)d_in[5];
    const float* g0ad = (const float*)d_in[6];
    const float* g0b  = (const float*)d_in[7];
    const float* g1w  = (const float*)d_in[8];
    const float* g1as = (const float*)d_in[9];
    const float* g1ad = (const float*)d_in[10];
    const float* g1b  = (const float*)d_in[11];
    const float* g2w  = (const float*)d_in[12];
    const float* g2as = (const float*)d_in[13];
    const float* g2ad = (const float*)d_in[14];
    const float* g2b  = (const float*)d_in[15];
    const float* cw   = (const float*)d_in[16];
    const float* cb   = (const float*)d_in[17];
    const float* ow   = (const float*)d_in[18];
    const float* ob   = (const float*)d_in[19];
    float* out = (float*)d_out;

    static cudaStream_t s2 = 0;
    static cudaEvent_t evFork = 0, evJoin = 0;
    static int ready = 0;
    if (!ready) {
        if (cudaStreamCreateWithFlags(&s2, cudaStreamNonBlocking) == cudaSuccess &&
            cudaEventCreateWithFlags(&evFork, cudaEventDisableTiming) == cudaSuccess &&
            cudaEventCreateWithFlags(&evJoin, cudaEventDisableTiming) == cudaSuccess)
            ready = 1;
        else
            ready = -1;
    }

    cudaFuncSetAttribute(k_gemm_mma<8>, cudaFuncAttributeMaxDynamicSharedMemorySize, GEMM_DYN);
    cudaFuncSetAttribute(k_gemm_mma<1>, cudaFuncAttributeMaxDynamicSharedMemorySize, GEMM_DYN);
    cudaFuncSetAttribute(k_conv, cudaFuncAttributeMaxDynamicSharedMemorySize, CONV_SMEM);

    if (ready == 1) {
        cudaEventRecord(evFork, 0);
        cudaStreamWaitEvent(s2, evFork, 0);
        k_hist<<<2501, 256, 0, s2>>>(ei, cw);
        k_scan<<<1, 1024, 0, s2>>>();
        k_scatter<<<(NE + 255) / 256, 256, 0, s2>>>(ei);
        k_sort<<<(NN + 7) / 8, 256, 0, s2>>>();
        cudaEventRecord(evJoin, s2);

        k_fold<<<1, 256>>>(pw, pb, g0w);
        k_gemm0_mma<<<NB * NN / 128, 256>>>(x, g0as, g0ad);
        cudaStreamWaitEvent(0, evJoin, 0);
    } else {
        k_hist<<<2501, 256>>>(ei, cw);
        k_scan<<<1, 1024>>>();
        k_scatter<<<(NE + 255) / 256, 256>>>(ei);
        k_sort<<<(NN + 7) / 8, 256>>>();
        k_fold<<<1, 256>>>(pw, pb, g0w);
        k_gemm0_mma<<<NB * NN / 128, 256>>>(x, g0as, g0ad);
    }

    launch_pdl(k_agg1p<8, true>, dim3(NN / 8), dim3(256), 0, g0b, 0);
    launch_pdl(k_gemm_mma<8>, dim3(NB * NN / 128), dim3(256), (size_t)GEMM_DYN, g1w, g1as, g1ad, 1);
    launch_pdl(k_agg1p<8, true>, dim3(NN / 8), dim3(256), 0, g1b, 1);
    launch_pdl(k_gemm_mma<1>, dim3(NB * NN / 128), dim3(256), (size_t)GEMM_DYN, g2w, g2as, g2ad, 2);
    launch_pdl(k_agg1p<1, false>, dim3(NN / 8), dim3(256), 0, g2b, 2);
    launch_pdl(k_conv, dim3((NN + CM - 1) / CM, NB), dim3(256), (size_t)CONV_SMEM, cb, ow, ob, out);
}

// round 15
// speedup vs baseline: 1.0110x; 1.0110x over previous
#include <cuda_runtime.h>
#include <cuda_fp16.h>
#include <math.h>

#define NN 20000
#define NE 640000
#define NB 4
#define NS 12
#define HD 64
#define DEG_CAP 96
#define FULL 0xffffffffu

// ---------------- scratch ----------------
//  g_h   [b*NN + n][64]          (fp32)
//  g_xeh [(n*NB + b)*32 + c]     (half2; 512 B per node covering 4 batches)
//  g_es  H=8: [n*32 + b*8 + h] ; H=1: [n*4 + b]     (g_ed same)
__device__ float    g_h [NB * NN * HD];
__device__ __half2  g_xeh[NB * NN * 32];
__device__ float    g_es[NB * NN * 8];
__device__ float    g_ed[NB * NN * 8];
__device__ unsigned g_mx[3][32];          // per-layer encoded max of es per (b,h)
__device__ float    g_fold[16 * 64];      // pw @ W0 (rows 12..15 zero)
__device__ float    g_cfold[64];          // pb @ W0
__device__ unsigned g_cwt[192 * 65];      // conv weights, tf32, padded transposed
__device__ int      g_cnt[NN];            // zero-init at load; scan re-zeroes each run
__device__ int      g_rank[NE];
__device__ int      g_rowptr[NN + 1];
__device__ int      g_csr[NE];

__device__ __forceinline__ float lrelu(float v) { return v > 0.f ? v : 0.2f * v; }

// order-preserving float<->uint encode for atomicMax
__device__ __forceinline__ unsigned encf(float f) {
    unsigned u = __float_as_uint(f);
    return (u & 0x80000000u) ? ~u : (u | 0x80000000u);
}
__device__ __forceinline__ float decf(unsigned u) {
    return (u & 0x80000000u) ? __uint_as_float(u ^ 0x80000000u) : __uint_as_float(~u);
}

__device__ __forceinline__ unsigned f2tf32(float v) {
    unsigned u;
    asm("cvt.rna.tf32.f32 %0, %1;" : "=r"(u) : "f"(v));
    return u;
}

__device__ __forceinline__ void mma_tf32(float c[4], unsigned a0, unsigned a1,
                                         unsigned a2, unsigned a3,
                                         unsigned b0, unsigned b1) {
    asm("mma.sync.aligned.m16n8k8.row.col.f32.tf32.tf32.f32 "
        "{%0,%1,%2,%3},{%4,%5,%6,%7},{%8,%9},{%0,%1,%2,%3};"
        : "+f"(c[0]), "+f"(c[1]), "+f"(c[2]), "+f"(c[3])
        : "r"(a0), "r"(a1), "r"(a2), "r"(a3), "r"(b0), "r"(b1));
}

// ---------------- CSR build (side-stream branch) ----------------
// blocks 0..2499: histogram; block 2500: convert conv weights to tf32 (independent)
__global__ __launch_bounds__(256) void k_hist(const int* __restrict__ ei,
                                              const float* __restrict__ cw) {
    if (blockIdx.x < 2500) {
        int e = blockIdx.x * 256 + threadIdx.x;
        if (e < NE) g_rank[e] = atomicAdd(&g_cnt[ei[NE + e]], 1);
    } else {
        for (int t = threadIdx.x; t < 64 * 192; t += 256) {
            int o = t / 192, ka = t % 192;
            g_cwt[ka * 65 + o] = f2tf32(cw[t]);
        }
    }
}

// scan consumes g_cnt and re-zeroes it (zero-on-entry invariant maintained)
__global__ __launch_bounds__(1024) void k_scan() {
    __shared__ int sh[1024];
    int t = threadIdx.x;
    const int CH = (NN + 1023) / 1024;
    int base = t * CH;
    int s = 0;
    for (int j = 0; j < CH; j++) {
        int idx = base + j;
        if (idx < NN) s += g_cnt[idx];
    }
    sh[t] = s;
    __syncthreads();
    for (int d = 1; d < 1024; d <<= 1) {
        int v = (t >= d) ? sh[t - d] : 0;
        __syncthreads();
        sh[t] += v;
        __syncthreads();
    }
    int run = sh[t] - s;
    for (int j = 0; j < CH; j++) {
        int idx = base + j;
        if (idx < NN) {
            int c = g_cnt[idx];
            g_rowptr[idx] = run;
            run += c;
            g_cnt[idx] = 0;
        }
    }
    if (t == 1023) g_rowptr[NN] = sh[1023];
}

__global__ __launch_bounds__(256) void k_scatter(const int* __restrict__ ei) {
    int e = blockIdx.x * 256 + threadIdx.x;
    if (e < NE) {
        int d = ei[NE + e];
        g_csr[g_rowptr[d] + g_rank[e]] = ei[e];
    }
}

// deterministic value-sort per node: single-pass rank counting (no sync chain)
__global__ __launch_bounds__(256) void k_sort() {
    __shared__ int s_v[8][DEG_CAP];
    int w = threadIdx.x >> 5, lane = threadIdx.x & 31;
    int node = blockIdx.x * 8 + w;
    if (node >= NN) return;
    int start = g_rowptr[node];
    int deg = g_rowptr[node + 1] - start;
    if (deg <= 1) return;
    if (deg <= DEG_CAP) {
        for (int j = lane; j < deg; j += 32) s_v[w][j] = g_csr[start + j];
        __syncwarp();
        for (int j = lane; j < deg; j += 32) {
            int v = s_v[w][j];
            int pos = 0;
            for (int k = 0; k < deg; k++) {
                int u = s_v[w][k];              // broadcast LDS
                pos += (u < v) || (u == v && k < j);
            }
            g_csr[start + pos] = v;
        }
    } else if (lane == 0) {   // statistically impossible fallback
        for (int a = start + 1; a < start + deg; a++) {
            int v = g_csr[a];
            int b = a - 1;
            while (b >= start && g_csr[b] > v) { g_csr[b + 1] = g_csr[b]; b--; }
            g_csr[b + 1] = v;
        }
    }
}

// ---------------- fold (main-stream branch): pw@W0, pb@W0; zeroes g_mx ----------------
__global__ __launch_bounds__(256) void k_fold(const float* __restrict__ pw,
                                              const float* __restrict__ pb,
                                              const float* __restrict__ W) {
    int tid = threadIdx.x;
    if (tid < 96) ((unsigned*)g_mx)[tid] = 0;   // before any gemm atomicMax (same stream)
    for (int i = tid; i < 1024; i += 256) {
        int s = i >> 6, o = i & 63;
        float acc = 0.f;
        if (s < NS)
            for (int k = 0; k < 64; k++) acc += pw[s * 64 + k] * W[k * 64 + o];
        g_fold[i] = acc;
    }
    if (tid < 64) {
        float a = 0.f;
        for (int k = 0; k < 64; k++) a += pb[k] * W[k * 64 + tid];
        g_cfold[tid] = a;
    }
}

// ---------------- mma gemm epilogue: xeh store + es/ed dots + max ----------------
template <int H>
__device__ __forceinline__ void mma_epilogue(float c[8][4], int n0, int b, int lane,
                                             const float2* as_sh, const float2* ad_sh,
                                             unsigned* smax_sh, int which) {
    int g = lane >> 2, tq = lane & 3;
    int nA = n0 + g, nB = n0 + g + 8;
    #pragma unroll
    for (int nt = 0; nt < 8; nt++) {
        g_xeh[((size_t)nA * NB + b) * 32 + nt * 4 + tq] = __floats2half2_rn(c[nt][0], c[nt][1]);
        g_xeh[((size_t)nB * NB + b) * 32 + nt * 4 + tq] = __floats2half2_rn(c[nt][2], c[nt][3]);
    }
    if (H == 8) {
        float keep[8];
        #pragma unroll
        for (int nt = 0; nt < 8; nt++) {
            float2 av = as_sh[nt * 4 + tq];
            float2 dv = ad_sh[nt * 4 + tq];
            float eA = c[nt][0] * av.x + c[nt][1] * av.y;
            float eB = c[nt][2] * av.x + c[nt][3] * av.y;
            float dA = c[nt][0] * dv.x + c[nt][1] * dv.y;
            float dB = c[nt][2] * dv.x + c[nt][3] * dv.y;
            eA += __shfl_xor_sync(FULL, eA, 1); eA += __shfl_xor_sync(FULL, eA, 2);
            eB += __shfl_xor_sync(FULL, eB, 1); eB += __shfl_xor_sync(FULL, eB, 2);
            dA += __shfl_xor_sync(FULL, dA, 1); dA += __shfl_xor_sync(FULL, dA, 2);
            dB += __shfl_xor_sync(FULL, dB, 1); dB += __shfl_xor_sync(FULL, dB, 2);
            if ((nt & 3) == tq) {
                int hi = nt >> 2;
                keep[hi * 4 + 0] = eA; keep[hi * 4 + 1] = eB;
                keep[hi * 4 + 2] = dA; keep[hi * 4 + 3] = dB;
            }
        }
        g_es[(size_t)nA * 32 + b * 8 + tq]     = keep[0];
        g_es[(size_t)nB * 32 + b * 8 + tq]     = keep[1];
        g_ed[(size_t)nA * 32 + b * 8 + tq]     = keep[2];
        g_ed[(size_t)nB * 32 + b * 8 + tq]     = keep[3];
        g_es[(size_t)nA * 32 + b * 8 + tq + 4] = keep[4];
        g_es[(size_t)nB * 32 + b * 8 + tq + 4] = keep[5];
        g_ed[(size_t)nA * 32 + b * 8 + tq + 4] = keep[6];
        g_ed[(size_t)nB * 32 + b * 8 + tq + 4] = keep[7];
        float mA = fmaxf(keep[0], keep[1]);
        float mB = fmaxf(keep[4], keep[5]);
        #pragma unroll
        for (int d = 4; d < 32; d <<= 1) {
            mA = fmaxf(mA, __shfl_xor_sync(FULL, mA, d));
            mB = fmaxf(mB, __shfl_xor_sync(FULL, mB, d));
        }
        if (g == 0) {
            atomicMax(&smax_sh[which * 8 + tq], encf(mA));
            atomicMax(&smax_sh[which * 8 + tq + 4], encf(mB));
        }
    } else {
        float eA = 0.f, eB = 0.f, dA = 0.f, dB = 0.f;
        #pragma unroll
        for (int nt = 0; nt < 8; nt++) {
            float2 av = as_sh[nt * 4 + tq];
            float2 dv = ad_sh[nt * 4 + tq];
            eA += c[nt][0] * av.x + c[nt][1] * av.y;
            eB += c[nt][2] * av.x + c[nt][3] * av.y;
            dA += c[nt][0] * dv.x + c[nt][1] * dv.y;
            dB += c[nt][2] * dv.x + c[nt][3] * dv.y;
        }
        eA += __shfl_xor_sync(FULL, eA, 1); eA += __shfl_xor_sync(FULL, eA, 2);
        eB += __shfl_xor_sync(FULL, eB, 1); eB += __shfl_xor_sync(FULL, eB, 2);
        dA += __shfl_xor_sync(FULL, dA, 1); dA += __shfl_xor_sync(FULL, dA, 2);
        dB += __shfl_xor_sync(FULL, dB, 1); dB += __shfl_xor_sync(FULL, dB, 2);
        if (tq == 0) {
            g_es[(size_t)nA * 4 + b] = eA;
            g_es[(size_t)nB * 4 + b] = eB;
            g_ed[(size_t)nA * 4 + b] = dA;
            g_ed[(size_t)nB * 4 + b] = dB;
        }
        float m = fmaxf(eA, eB);
        #pragma unroll
        for (int d = 4; d < 32; d <<= 1) m = fmaxf(m, __shfl_xor_sync(FULL, m, d));
        if (lane == 0) atomicMax(&smax_sh[which * 8], encf(m));
    }
}

// ---------------- gemm layers 1,2: xe = h @ W via tf32 mma ----------------
#define GEMM_DYN ((4096 + 8 * 1088) * 4)

template <int H>
__global__ __launch_bounds__(256) void k_gemm_mma(const float* __restrict__ W,
                                                  const float* __restrict__ asrc,
                                                  const float* __restrict__ adst,
                                                  int layer) {
    extern __shared__ unsigned dynsh[];
    uint2* wfrag = (uint2*)dynsh;              // 8 kc x 8 nt x 32 lanes
    unsigned* hst = dynsh + 4096;              // 8 warps x 16 nodes x 68 pad
    __shared__ float2 as_sh[32], ad_sh[32];
    __shared__ unsigned smax_sh[16];
    int tid = threadIdx.x, w = tid >> 5, lane = tid & 31, g = lane >> 2, tq = lane & 3;
    for (int i = tid; i < 4096; i += 256) {
        int k = i >> 6, o = i & 63;
        unsigned val = f2tf32(__ldg(&W[i]));
        int slot = ((k >> 3) * 8 + (o >> 3)) * 32 + (o & 7) * 4 + (k & 3);
        ((unsigned*)wfrag)[slot * 2 + ((k >> 2) & 1)] = val;
    }
    if (tid < 32) { as_sh[tid] = ((const float2*)asrc)[tid]; ad_sh[tid] = ((const float2*)adst)[tid]; }
    if (tid < 16) smax_sh[tid] = 0;
    int idxw = blockIdx.x * 128 + w * 16;
    int b = idxw / NN, n0 = idxw - b * NN;
    {
        const float4* gh4 = (const float4*)g_h;
        uint4* hs4 = (uint4*)(hst + w * 1088);
        #pragma unroll
        for (int j = 0; j < 8; j++) {
            int i4 = lane + 32 * j;
            int node = i4 >> 4, c4 = i4 & 15;
            float4 v = gh4[((size_t)idxw + node) * 16 + c4];
            uint4 u;
            u.x = f2tf32(v.x); u.y = f2tf32(v.y); u.z = f2tf32(v.z); u.w = f2tf32(v.w);
            hs4[node * 17 + c4] = u;
        }
    }
    __syncthreads();
    float c[8][4];
    #pragma unroll
    for (int nt = 0; nt < 8; nt++)
        c[nt][0] = c[nt][1] = c[nt][2] = c[nt][3] = 0.f;
    unsigned* hs = hst + w * 1088;
    #pragma unroll
    for (int kc = 0; kc < 8; kc++) {
        unsigned a0 = hs[g * 68 + kc * 8 + tq];
        unsigned a1 = hs[(g + 8) * 68 + kc * 8 + tq];
        unsigned a2 = hs[g * 68 + kc * 8 + tq + 4];
        unsigned a3 = hs[(g + 8) * 68 + kc * 8 + tq + 4];
        #pragma unroll
        for (int nt = 0; nt < 8; nt++) {
            uint2 bb = wfrag[(kc * 8 + nt) * 32 + lane];
            mma_tf32(c[nt], a0, a1, a2, a3, bb.x, bb.y);
        }
    }
    int bfirst = (blockIdx.x * 128) / NN;
    mma_epilogue<H>(c, n0, b, lane, as_sh, ad_sh, smax_sh, b - bfirst);
    __syncthreads();
    if (tid < 16) {
        int which = tid >> 3, h = tid & 7;
        int bt = bfirst + which;
        unsigned v = smax_sh[tid];
        if (bt < NB && v != 0 && (H == 8 || h == 0))
            atomicMax(&g_mx[layer][(H == 8) ? bt * 8 + h : bt], v);
    }
}

// ---------------- layer 0: xe = X @ (pw W) + pb W via tf32 mma (K=16) ----------------
__global__ __launch_bounds__(256) void k_gemm0_mma(const float* __restrict__ x,
                                                   const float* __restrict__ asrc,
                                                   const float* __restrict__ adst) {
    __shared__ uint2 wfrag[512];               // 2 kc x 8 nt x 32
    __shared__ unsigned xst[8][320];           // 16 nodes x 20 pad per warp
    __shared__ float2 as_sh[32], ad_sh[32];
    __shared__ float cf_sh[64];
    __shared__ unsigned smax_sh[16];
    int tid = threadIdx.x, w = tid >> 5, lane = tid & 31, g = lane >> 2, tq = lane & 3;
    for (int i = tid; i < 1024; i += 256) {
        int k = i >> 6, o = i & 63;
        unsigned val = f2tf32(g_fold[i]);
        int slot = ((k >> 3) * 8 + (o >> 3)) * 32 + (o & 7) * 4 + (k & 3);
        ((unsigned*)wfrag)[slot * 2 + ((k >> 2) & 1)] = val;
    }
    if (tid < 32) { as_sh[tid] = ((const float2*)asrc)[tid]; ad_sh[tid] = ((const float2*)adst)[tid]; }
    if (tid < 64) cf_sh[tid] = g_cfold[tid];
    if (tid < 16) smax_sh[tid] = 0;
    int idxw = blockIdx.x * 128 + w * 16;
    int b = idxw / NN, n0 = idxw - b * NN;
    #pragma unroll
    for (int j = 0; j < 8; j++) {
        int i2 = lane + 32 * j;                // s = i2>>4 (0..15), node = i2&15
        int s = i2 >> 4, node = i2 & 15;
        unsigned val = 0;
        if (s < NS) val = f2tf32(__ldg(&x[(size_t)(b * NS + s) * NN + n0 + node]));
        xst[w][node * 20 + s] = val;
    }
    __syncthreads();
    float c[8][4];
    #pragma unroll
    for (int nt = 0; nt < 8; nt++)
        c[nt][0] = c[nt][1] = c[nt][2] = c[nt][3] = 0.f;
    #pragma unroll
    for (int kc = 0; kc < 2; kc++) {
        unsigned a0 = xst[w][g * 20 + kc * 8 + tq];
        unsigned a1 = xst[w][(g + 8) * 20 + kc * 8 + tq];
        unsigned a2 = xst[w][g * 20 + kc * 8 + tq + 4];
        unsigned a3 = xst[w][(g + 8) * 20 + kc * 8 + tq + 4];
        #pragma unroll
        for (int nt = 0; nt < 8; nt++) {
            uint2 bb = wfrag[(kc * 8 + nt) * 32 + lane];
            mma_tf32(c[nt], a0, a1, a2, a3, bb.x, bb.y);
        }
    }
    #pragma unroll
    for (int nt = 0; nt < 8; nt++) {
        float c0 = cf_sh[nt * 8 + 2 * tq], c1 = cf_sh[nt * 8 + 2 * tq + 1];
        c[nt][0] += c0; c[nt][1] += c1;
        c[nt][2] += c0; c[nt][3] += c1;
    }
    int bfirst = (blockIdx.x * 128) / NN;
    mma_epilogue<8>(c, n0, b, lane, as_sh, ad_sh, smax_sh, b - bfirst);
    __syncthreads();
    if (tid < 16) {
        int which = tid >> 3, h = tid & 7;
        int bt = bfirst + which;
        unsigned v = smax_sh[tid];
        if (bt < NB && v != 0)
            atomicMax(&g_mx[0][bt * 8 + h], v);
    }
}

// ---------------- single-pass 4-batch aggregation (R6 proven form) ----------------
template <int H, bool DO_ELU>
__global__ __launch_bounds__(256) void k_agg1p(const float* __restrict__ bias, int layer) {
    int w = threadIdx.x >> 5, lane = threadIdx.x & 31;
    int i = blockIdx.x * 8 + w;
    int start = g_rowptr[i];
    int deg = g_rowptr[i + 1] - start;
    int tot = deg + 1;                       // + self loop
    int b3 = lane >> 3, ch = lane & 7;
    float edv, m;
    if (H == 8) {
        edv = __ldg(&g_ed[(size_t)i * 32 + lane]);
        m = lrelu(decf(g_mx[layer][lane]) + edv);
    } else {
        edv = __ldg(&g_ed[(size_t)i * 4 + b3]);
        m = lrelu(decf(g_mx[2][b3]) + edv);
    }
    float sum = 0.f;
    float a[8];
    #pragma unroll
    for (int k = 0; k < 8; k++) a[k] = 0.f;
    const uint4* __restrict__ xe4 = (const uint4*)g_xeh;
    const int* __restrict__ csr = g_csr + start;

    #pragma unroll 4
    for (int j = 0; j < tot; j++) {
        int s = (j < deg) ? __ldg(&csr[j]) : i;
        float e = (H == 8) ? __ldg(&g_es[(size_t)s * 32 + lane])
                           : __ldg(&g_es[(size_t)s * 4 + b3]);
        float p = __expf(lrelu(e + edv) - m);
        sum += p;
        uint4 v = __ldg(&xe4[(size_t)s * 32 + lane]);
        float2 f0 = __half22float2(*(const __half2*)&v.x);
        float2 f1 = __half22float2(*(const __half2*)&v.y);
        float2 f2 = __half22float2(*(const __half2*)&v.z);
        float2 f3 = __half22float2(*(const __half2*)&v.w);
        a[0] += p * f0.x; a[1] += p * f0.y;
        a[2] += p * f1.x; a[3] += p * f1.y;
        a[4] += p * f2.x; a[5] += p * f2.y;
        a[6] += p * f3.x; a[7] += p * f3.y;
    }

    float inv = 1.f / sum;
    float4 bb0 = ((const float4*)bias)[ch * 2];
    float4 bb1 = ((const float4*)bias)[ch * 2 + 1];
    float o[8];
    o[0] = a[0] * inv + bb0.x; o[1] = a[1] * inv + bb0.y;
    o[2] = a[2] * inv + bb0.z; o[3] = a[3] * inv + bb0.w;
    o[4] = a[4] * inv + bb1.x; o[5] = a[5] * inv + bb1.y;
    o[6] = a[6] * inv + bb1.z; o[7] = a[7] * inv + bb1.w;
    if (DO_ELU) {
        #pragma unroll
        for (int k = 0; k < 8; k++) o[k] = o[k] > 0.f ? o[k] : expm1f(o[k]);
    }
    float4* gh4 = (float4*)g_h;
    size_t obase = ((size_t)(b3 * NN + i)) * 16 + ch * 2;
    gh4[obase]     = make_float4(o[0], o[1], o[2], o[3]);
    gh4[obase + 1] = make_float4(o[4], o[5], o[6], o[7]);
}

// ---------------- conv1d(k=3) + relu + head via tf32 mma ----------------
#define CM 128
#define W_ELE (192 * 65)
#define H_ELE (130 * 65)
#define CONV_SMEM ((W_ELE + H_ELE + 192 + 64) * 4)

__global__ __launch_bounds__(256) void k_conv(const float* __restrict__ cb,
                                              const float* __restrict__ ow,
                                              const float* __restrict__ ob,
                                              float* __restrict__ out) {
    extern __shared__ unsigned cms[];
    unsigned* w_sh = cms;
    unsigned* h_sh = w_sh + W_ELE;
    float* ow_sh = (float*)(h_sh + H_ELE);
    float* cb_sh = ow_sh + 192;
    int tid = threadIdx.x;
    int b = blockIdx.y;
    int n0 = blockIdx.x * CM;

    {
        const uint4* src = (const uint4*)g_cwt;
        uint4* dst = (uint4*)w_sh;
        for (int t = tid; t < W_ELE / 4; t += 256) dst[t] = src[t];
    }
    for (int t = tid; t < 130 * 64; t += 256) {
        int row = t / 64, c = t % 64;
        int n = n0 - 1 + row;
        float v = (n >= 0 && n < NN) ? g_h[((size_t)(b * NN + n)) * 64 + c] : 0.f;
        h_sh[row * 65 + c] = f2tf32(v);
    }
    if (tid < 192) ow_sh[tid] = ow[tid];
    if (tid < 64) cb_sh[tid] = cb[tid];
    __syncthreads();

    int wz = tid >> 5, lane = tid & 31;
    int m0 = wz * 16;
    int g = lane >> 2, tq = lane & 3;
    float c[8][4];
    #pragma unroll
    for (int t = 0; t < 8; t++)
        #pragma unroll
        for (int r = 0; r < 4; r++) c[t][r] = 0.f;

    #pragma unroll 4
    for (int kc = 0; kc < 24; kc++) {
        int ka = kc * 8 + tq;
        int ia = ka / 3, sa = ka % 3;
        int kb = ka + 4;
        int ib = kb / 3, sb = kb % 3;
        unsigned a0 = h_sh[(m0 + g + sa) * 65 + ia];
        unsigned a1 = h_sh[(m0 + g + 8 + sa) * 65 + ia];
        unsigned a2 = h_sh[(m0 + g + sb) * 65 + ib];
        unsigned a3 = h_sh[(m0 + g + 8 + sb) * 65 + ib];
        #pragma unroll
        for (int t = 0; t < 8; t++) {
            unsigned b0 = w_sh[(kc * 8 + tq) * 65 + 8 * t + g];
            unsigned b1 = w_sh[(kc * 8 + tq + 4) * 65 + 8 * t + g];
            mma_tf32(c[t], a0, a1, a2, a3, b0, b1);
        }
    }
    __syncthreads();

    float* v_sh = (float*)h_sh;
    #pragma unroll
    for (int t = 0; t < 8; t++) {
        int n_ = 8 * t + 2 * tq;
        v_sh[(m0 + g) * 65 + n_]     = fmaxf(c[t][0] + cb_sh[n_], 0.f);
        v_sh[(m0 + g) * 65 + n_ + 1] = fmaxf(c[t][1] + cb_sh[n_ + 1], 0.f);
        v_sh[(m0 + g + 8) * 65 + n_]     = fmaxf(c[t][2] + cb_sh[n_], 0.f);
        v_sh[(m0 + g + 8) * 65 + n_ + 1] = fmaxf(c[t][3] + cb_sh[n_ + 1], 0.f);
    }
    __syncthreads();

    float ob0 = ob[0], ob1 = ob[1], ob2 = ob[2];
    for (int task = tid; task < CM * 3; task += 256) {
        int mloc = task / 3, p = task % 3;
        int n = n0 + mloc;
        if (n < NN) {
            float acc = (p == 0) ? ob0 : (p == 1 ? ob1 : ob2);
            #pragma unroll 16
            for (int o = 0; o < 64; o++)
                acc += v_sh[mloc * 65 + o] * ow_sh[o * 3 + p];
            out[((size_t)(b * 3 + p)) * NN + n] = acc;
        }
    }
}

// ---------------- driver: fork CSR chain onto side stream, join before agg0 ----------------
extern "C" void kernel_launch(void* const* d_in, const int* in_sizes, int n_in,
                              void* d_out, int out_size) {
    const float* x    = (const float*)d_in[0];
    const int*   ei   = (const int*)d_in[1];
    const float* pw   = (const float*)d_in[2];
    const float* pb   = (const float*)d_in[3];
    const float* g0w  = (const float*)d_in[4];
    const float* g0as = (const float*)d_in[5];
    const float* g0ad = (const float*)d_in[6];
    const float* g0b  = (const float*)d_in[7];
    const float* g1w  = (const float*)d_in[8];
    const float* g1as = (const float*)d_in[9];
    const float* g1ad = (const float*)d_in[10];
    const float* g1b  = (const float*)d_in[11];
    const float* g2w  = (const float*)d_in[12];
    const float* g2as = (const float*)d_in[13];
    const float* g2ad = (const float*)d_in[14];
    const float* g2b  = (const float*)d_in[15];
    const float* cw   = (const float*)d_in[16];
    const float* cb   = (const float*)d_in[17];
    const float* ow   = (const float*)d_in[18];
    const float* ob   = (const float*)d_in[19];
    float* out = (float*)d_out;

    // one-time side-stream infrastructure (no device-memory allocation)
    static cudaStream_t s2 = 0;
    static cudaEvent_t evFork = 0, evJoin = 0;
    static int ready = 0;
    if (!ready) {
        if (cudaStreamCreateWithFlags(&s2, cudaStreamNonBlocking) == cudaSuccess &&
            cudaEventCreateWithFlags(&evFork, cudaEventDisableTiming) == cudaSuccess &&
            cudaEventCreateWithFlags(&evJoin, cudaEventDisableTiming) == cudaSuccess)
            ready = 1;
        else
            ready = -1;   // fall back to fully serial launches
    }

    cudaFuncSetAttribute(k_gemm_mma<8>, cudaFuncAttributeMaxDynamicSharedMemorySize, GEMM_DYN);
    cudaFuncSetAttribute(k_gemm_mma<1>, cudaFuncAttributeMaxDynamicSharedMemorySize, GEMM_DYN);
    cudaFuncSetAttribute(k_conv, cudaFuncAttributeMaxDynamicSharedMemorySize, CONV_SMEM);

    if (ready == 1) {
        // fork: CSR chain on s2, fold+gemm0 on main stream
        cudaEventRecord(evFork, 0);
        cudaStreamWaitEvent(s2, evFork, 0);
        k_hist<<<2501, 256, 0, s2>>>(ei, cw);
        k_scan<<<1, 1024, 0, s2>>>();
        k_scatter<<<(NE + 255) / 256, 256, 0, s2>>>(ei);
        k_sort<<<(NN + 7) / 8, 256, 0, s2>>>();
        cudaEventRecord(evJoin, s2);

        k_fold<<<1, 256>>>(pw, pb, g0w);      // zeroes g_mx, then fold
        k_gemm0_mma<<<NB * NN / 128, 256>>>(x, g0as, g0ad);
        cudaStreamWaitEvent(0, evJoin, 0);    // join before agg0
    } else {
        k_hist<<<2501, 256>>>(ei, cw);
        k_scan<<<1, 1024>>>();
        k_scatter<<<(NE + 255) / 256, 256>>>(ei);
        k_sort<<<(NN + 7) / 8, 256>>>();
        k_fold<<<1, 256>>>(pw, pb, g0w);
        k_gemm0_mma<<<NB * NN / 128, 256>>>(x, g0as, g0ad);
    }

    k_agg1p<8, true><<<NN / 8, 256>>>(g0b, 0);
    k_gemm_mma<8><<<NB * NN / 128, 256, GEMM_DYN>>>(g1w, g1as, g1ad, 1);
    k_agg1p<8, true><<<NN / 8, 256>>>(g1b, 1);
    k_gemm_mma<1><<<NB * NN / 128, 256, GEMM_DYN>>>(g2w, g2as, g2ad, 2);
    k_agg1p<1, false><<<NN / 8, 256>>>(g2b, 2);

    k_conv<<<dim3((NN + CM - 1) / CM, NB), 256, CONV_SMEM>>>(cb, ow, ob, out);
}